// round 1
// baseline (speedup 1.0000x reference)
#include <cuda_runtime.h>

#define NN 50000
#define NE 800000
#define D  128
#define NG 128

// ---------------- device scratch (static, allocation-free) ----------------
__device__ float g_z[NN * D];     // z = (1+eps)h + agg, input to MLP
__device__ float g_hA[NN * D];    // ping
__device__ float g_hB[NN * D];    // pong
__device__ int   g_rowptr[NN + 1];
__device__ int   g_pos[NN];
__device__ int   g_cnt[NN];
__device__ int   g_col[NE];

// ---------------- CSR build ----------------
__global__ void k_zero_cnt() {
    int i = blockIdx.x * blockDim.x + threadIdx.x;
    if (i < NN) g_cnt[i] = 0;
}

__global__ void k_count(const int* __restrict__ dst) {
    int e = blockIdx.x * blockDim.x + threadIdx.x;
    if (e < NE) atomicAdd(&g_cnt[dst[e]], 1);
}

// single-block Hillis-Steele scan over 50000 counts -> rowptr (incl) + pos (excl)
__global__ void k_scan() {
    __shared__ int s[1024];
    int t = threadIdx.x;
    int carry = 0;
    for (int start = 0; start < NN; start += 1024) {
        int i = start + t;
        int v = (i < NN) ? g_cnt[i] : 0;
        s[t] = v;
        __syncthreads();
        for (int off = 1; off < 1024; off <<= 1) {
            int x = (t >= off) ? s[t - off] : 0;
            __syncthreads();
            s[t] += x;
            __syncthreads();
        }
        int incl = s[t];
        if (i < NN) {
            g_rowptr[i + 1] = carry + incl;
            g_pos[i]        = carry + incl - v;
        }
        carry += s[1023];
        __syncthreads();
    }
    if (t == 0) g_rowptr[0] = 0;
}

__global__ void k_scatter(const int* __restrict__ src, const int* __restrict__ dst) {
    int e = blockIdx.x * blockDim.x + threadIdx.x;
    if (e < NE) {
        int d = dst[e];
        int p = atomicAdd(&g_pos[d], 1);
        g_col[p] = src[e];
    }
}

// ---------------- aggregation: z = (1+eps)*h + sum_{src in N(v)} h[src] ----------------
// one warp per node; lane owns a float4 (4 cols). CSR gather, no atomics.
__global__ void k_agg(const float* __restrict__ feats, const float* __restrict__ eps,
                      int layer, int sel) {
    int gt   = blockIdx.x * blockDim.x + threadIdx.x;
    int w    = gt >> 5;
    int lane = gt & 31;
    if (w >= NN) return;

    const float* h = (sel == 0) ? feats : (sel == 1 ? g_hA : g_hB);
    const float4* hv = (const float4*)h;

    float ev = 1.0f + __ldg(&eps[layer]);
    float4 a = __ldg(&hv[w * 32 + lane]);
    a.x *= ev; a.y *= ev; a.z *= ev; a.w *= ev;

    int b = g_rowptr[w];
    int e = g_rowptr[w + 1];
    for (int j = b; j < e; j++) {
        int s = g_col[j];                      // broadcast load across warp
        float4 x = __ldg(&hv[s * 32 + lane]);  // 512B coalesced row read (L2-resident)
        a.x += x.x; a.y += x.y; a.z += x.z; a.w += x.w;
    }
    ((float4*)g_z)[w * 32 + lane] = a;
}

// ---------------- fused 2-layer MLP: h_out = relu(z@W1+b1)@W2 + b2 ----------------
// 128-row tile per block, 256 threads, 8x8 register micro-tile per thread.
// Zs/Ts stored k-major with stride 129 (conflict-free), Ws k-major stride 128 (float4 reads).
#define MLP_SMEM ((128 * 129 + 128 * 128 + 128 * 129) * 4)

__global__ void __launch_bounds__(256, 1)
k_mlp(const float* __restrict__ W1, const float* __restrict__ B1,
      const float* __restrict__ W2, const float* __restrict__ B2,
      int outsel) {
    extern __shared__ float sm[];
    float* Zs = sm;                          // [k=128][r stride 129]
    float* Ws = sm + 128 * 129;              // [k=128][c=128]
    float* Ts = sm + 128 * 129 + 128 * 128;  // [c=128][r stride 129]

    float* hout = (outsel == 1) ? g_hA : g_hB;

    int t  = threadIdx.x;
    int tx = t & 15;   // col group: cols tx*8 .. tx*8+7
    int ty = t >> 4;   // row group: rows ty*8 .. ty*8+7
    int row0 = blockIdx.x * 128;

    // load z tile (transposed into Zs) -- coalesced float4 global reads
    #pragma unroll
    for (int i = 0; i < 16; i++) {
        int idx = (i * 256 + t) * 4;
        int k = idx & 127;
        int r = idx >> 7;
        int row = row0 + r;
        float4 v = make_float4(0.f, 0.f, 0.f, 0.f);
        if (row < NN) v = __ldg((const float4*)&g_z[row * 128 + k]);
        Zs[(k + 0) * 129 + r] = v.x;
        Zs[(k + 1) * 129 + r] = v.y;
        Zs[(k + 2) * 129 + r] = v.z;
        Zs[(k + 3) * 129 + r] = v.w;
    }
    // load W1
    {
        const float4* w4 = (const float4*)W1;
        float4* s4 = (float4*)Ws;
        #pragma unroll
        for (int i = 0; i < 16; i++) s4[i * 256 + t] = __ldg(&w4[i * 256 + t]);
    }
    __syncthreads();

    float acc[8][8];
    #pragma unroll
    for (int i = 0; i < 8; i++)
        #pragma unroll
        for (int j = 0; j < 8; j++) acc[i][j] = 0.f;

    // GEMM 1: t = z @ W1
    #pragma unroll 8
    for (int k = 0; k < 128; k++) {
        float a[8], b[8];
        #pragma unroll
        for (int i = 0; i < 8; i++) a[i] = Zs[k * 129 + ty * 8 + i];
        float4 b0 = *(const float4*)&Ws[k * 128 + tx * 8];
        float4 b1v = *(const float4*)&Ws[k * 128 + tx * 8 + 4];
        b[0] = b0.x; b[1] = b0.y; b[2] = b0.z; b[3] = b0.w;
        b[4] = b1v.x; b[5] = b1v.y; b[6] = b1v.z; b[7] = b1v.w;
        #pragma unroll
        for (int i = 0; i < 8; i++)
            #pragma unroll
            for (int j = 0; j < 8; j++) acc[i][j] = fmaf(a[i], b[j], acc[i][j]);
    }

    // epilogue 1: relu + bias, store transposed into Ts
    {
        float bb[8];
        #pragma unroll
        for (int j = 0; j < 8; j++) bb[j] = __ldg(&B1[tx * 8 + j]);
        #pragma unroll
        for (int j = 0; j < 8; j++)
            #pragma unroll
            for (int i = 0; i < 8; i++)
                Ts[(tx * 8 + j) * 129 + ty * 8 + i] = fmaxf(acc[i][j] + bb[j], 0.f);
    }
    __syncthreads();

    // load W2 (overwrite Ws)
    {
        const float4* w4 = (const float4*)W2;
        float4* s4 = (float4*)Ws;
        #pragma unroll
        for (int i = 0; i < 16; i++) s4[i * 256 + t] = __ldg(&w4[i * 256 + t]);
    }
    __syncthreads();

    #pragma unroll
    for (int i = 0; i < 8; i++)
        #pragma unroll
        for (int j = 0; j < 8; j++) acc[i][j] = 0.f;

    // GEMM 2: out = t @ W2
    #pragma unroll 8
    for (int k = 0; k < 128; k++) {
        float a[8], b[8];
        #pragma unroll
        for (int i = 0; i < 8; i++) a[i] = Ts[k * 129 + ty * 8 + i];
        float4 b0 = *(const float4*)&Ws[k * 128 + tx * 8];
        float4 b1v = *(const float4*)&Ws[k * 128 + tx * 8 + 4];
        b[0] = b0.x; b[1] = b0.y; b[2] = b0.z; b[3] = b0.w;
        b[4] = b1v.x; b[5] = b1v.y; b[6] = b1v.z; b[7] = b1v.w;
        #pragma unroll
        for (int i = 0; i < 8; i++)
            #pragma unroll
            for (int j = 0; j < 8; j++) acc[i][j] = fmaf(a[i], b[j], acc[i][j]);
    }

    // epilogue 2: bias, write to global
    {
        float bb[8];
        #pragma unroll
        for (int j = 0; j < 8; j++) bb[j] = __ldg(&B2[tx * 8 + j]);
        #pragma unroll
        for (int i = 0; i < 8; i++) {
            int row = row0 + ty * 8 + i;
            if (row < NN) {
                float4 v0 = make_float4(acc[i][0] + bb[0], acc[i][1] + bb[1],
                                        acc[i][2] + bb[2], acc[i][3] + bb[3]);
                float4 v1 = make_float4(acc[i][4] + bb[4], acc[i][5] + bb[5],
                                        acc[i][6] + bb[6], acc[i][7] + bb[7]);
                *(float4*)&hout[row * 128 + tx * 8]     = v0;
                *(float4*)&hout[row * 128 + tx * 8 + 4] = v1;
            }
        }
    }
}

// ---------------- graph sum pooling ----------------
__global__ void k_zero_out(float* __restrict__ out) {
    int i = blockIdx.x * blockDim.x + threadIdx.x;
    if (i < NG * D) out[i] = 0.f;
}

// graph_id is sorted: run-length accumulate within each 128-node block,
// flush with atomicAdd only at graph boundaries (rare).
__global__ void k_pool(const int* __restrict__ gid, float* __restrict__ out) {
    int c  = threadIdx.x;          // column 0..127
    int n0 = blockIdx.x * 128;
    float acc = 0.f;
    int cur = -1;
    for (int r = 0; r < 128; r++) {
        int n = n0 + r;
        if (n >= NN) break;
        int g = __ldg(&gid[n]);    // broadcast across block
        if (g != cur) {
            if (cur >= 0) atomicAdd(&out[cur * 128 + c], acc);
            cur = g;
            acc = 0.f;
        }
        acc += g_hA[n * 128 + c];  // coalesced
    }
    if (cur >= 0) atomicAdd(&out[cur * 128 + c], acc);
}

// ---------------- launch ----------------
extern "C" void kernel_launch(void* const* d_in, const int* in_sizes, int n_in,
                              void* d_out, int out_size) {
    const float* feats = (const float*)d_in[0];
    const int*   esrc  = (const int*)d_in[1];
    const int*   edst  = (const int*)d_in[2];
    const int*   gid   = (const int*)d_in[3];
    const float* eps   = (const float*)d_in[4];
    const float* W1[3] = {(const float*)d_in[5],  (const float*)d_in[9],  (const float*)d_in[13]};
    const float* B1[3] = {(const float*)d_in[6],  (const float*)d_in[10], (const float*)d_in[14]};
    const float* W2[3] = {(const float*)d_in[7],  (const float*)d_in[11], (const float*)d_in[15]};
    const float* B2[3] = {(const float*)d_in[8],  (const float*)d_in[12], (const float*)d_in[16]};
    float* out = (float*)d_out;
    (void)in_sizes; (void)n_in; (void)out_size;

    cudaFuncSetAttribute(k_mlp, cudaFuncAttributeMaxDynamicSharedMemorySize, MLP_SMEM);

    // CSR build (constant topology, but recomputed every call per determinism rules)
    k_zero_cnt<<<(NN + 255) / 256, 256>>>();
    k_count<<<(NE + 255) / 256, 256>>>(edst);
    k_scan<<<1, 1024>>>();
    k_scatter<<<(NE + 255) / 256, 256>>>(esrc, edst);

    int aggGrid = (NN * 32 + 255) / 256;
    int mlpGrid = (NN + 127) / 128;

    // layer 0: feats -> g_hA
    k_agg<<<aggGrid, 256>>>(feats, eps, 0, 0);
    k_mlp<<<mlpGrid, 256, MLP_SMEM>>>(W1[0], B1[0], W2[0], B2[0], 1);
    // layer 1: g_hA -> g_hB
    k_agg<<<aggGrid, 256>>>(feats, eps, 1, 1);
    k_mlp<<<mlpGrid, 256, MLP_SMEM>>>(W1[1], B1[1], W2[1], B2[1], 2);
    // layer 2: g_hB -> g_hA
    k_agg<<<aggGrid, 256>>>(feats, eps, 2, 2);
    k_mlp<<<mlpGrid, 256, MLP_SMEM>>>(W1[2], B1[2], W2[2], B2[2], 1);

    // pooling
    k_zero_out<<<(NG * D + 255) / 256, 256>>>(out);
    k_pool<<<(NN + 127) / 128, 128>>>(gid, out);
}

// round 2
// speedup vs baseline: 1.1504x; 1.1504x over previous
#include <cuda_runtime.h>

#define NN 50000
#define NE 800000
#define D  128
#define NG 128

// ---------------- device scratch (static, allocation-free) ----------------
__device__ float g_z[NN * D];     // z = (1+eps)h + agg, input to MLP
__device__ float g_hA[NN * D];    // ping
__device__ float g_hB[NN * D];    // pong
__device__ int   g_rowptr[NN + 1];
__device__ int   g_pos[NN];
__device__ int   g_cnt[NN];
__device__ int   g_col[NE];

// ---------------- CSR build ----------------
__global__ void k_zero_cnt() {
    int i = blockIdx.x * blockDim.x + threadIdx.x;
    if (i < NN) g_cnt[i] = 0;
}

__global__ void k_count(const int* __restrict__ dst) {
    int e = blockIdx.x * blockDim.x + threadIdx.x;
    if (e < NE) atomicAdd(&g_cnt[dst[e]], 1);
}

__global__ void k_scan() {
    __shared__ int s[1024];
    int t = threadIdx.x;
    int carry = 0;
    for (int start = 0; start < NN; start += 1024) {
        int i = start + t;
        int v = (i < NN) ? g_cnt[i] : 0;
        s[t] = v;
        __syncthreads();
        for (int off = 1; off < 1024; off <<= 1) {
            int x = (t >= off) ? s[t - off] : 0;
            __syncthreads();
            s[t] += x;
            __syncthreads();
        }
        int incl = s[t];
        if (i < NN) {
            g_rowptr[i + 1] = carry + incl;
            g_pos[i]        = carry + incl - v;
        }
        carry += s[1023];
        __syncthreads();
    }
    if (t == 0) g_rowptr[0] = 0;
}

__global__ void k_scatter(const int* __restrict__ src, const int* __restrict__ dst) {
    int e = blockIdx.x * blockDim.x + threadIdx.x;
    if (e < NE) {
        int d = dst[e];
        int p = atomicAdd(&g_pos[d], 1);
        g_col[p] = src[e];
    }
}

// ---------------- aggregation ----------------
__global__ void k_agg(const float* __restrict__ feats, const float* __restrict__ eps,
                      int layer, int sel) {
    int gt   = blockIdx.x * blockDim.x + threadIdx.x;
    int w    = gt >> 5;
    int lane = gt & 31;
    if (w >= NN) return;

    const float* h = (sel == 0) ? feats : (sel == 1 ? g_hA : g_hB);
    const float4* hv = (const float4*)h;

    float ev = 1.0f + __ldg(&eps[layer]);
    float4 a = __ldg(&hv[w * 32 + lane]);
    a.x *= ev; a.y *= ev; a.z *= ev; a.w *= ev;

    int b = g_rowptr[w];
    int e = g_rowptr[w + 1];
    for (int j = b; j < e; j++) {
        int s = g_col[j];
        float4 x = __ldg(&hv[s * 32 + lane]);
        a.x += x.x; a.y += x.y; a.z += x.z; a.w += x.w;
    }
    ((float4*)g_z)[w * 32 + lane] = a;
}

// ---------------- tensor-core fused MLP (3xTF32) ----------------
// A tiles stride 132 (4 mod 32 -> conflict-free m16k8 frag loads)
// W tiles stride 136 (8 mod 32 -> conflict-free k8n8 frag loads)
#define SA 132
#define SB 136
#define MLP_SMEM ((128 * SA + 2 * 128 * SB) * 4)   // 206848 B

__device__ __forceinline__ void mma_tf32(float* c, const unsigned* a, const unsigned* b) {
    asm volatile("mma.sync.aligned.m16n8k8.row.col.f32.tf32.tf32.f32 "
        "{%0,%1,%2,%3}, {%4,%5,%6,%7}, {%8,%9}, {%0,%1,%2,%3};"
        : "+f"(c[0]), "+f"(c[1]), "+f"(c[2]), "+f"(c[3])
        : "r"(a[0]), "r"(a[1]), "r"(a[2]), "r"(a[3]), "r"(b[0]), "r"(b[1]));
}

__device__ __forceinline__ void split_tf32(float x, float& hi, float& lo) {
    unsigned h;
    asm("cvt.rna.tf32.f32 %0, %1;" : "=r"(h) : "f"(x));
    hi = __uint_as_float(h);
    float lf = x - hi;
    unsigned l;
    asm("cvt.rna.tf32.f32 %0, %1;" : "=r"(l) : "f"(lf));
    lo = __uint_as_float(l);
}

// cooperative: load 128x128 W from global, split hi/lo into smem
__device__ __forceinline__ void load_w_split(const float* __restrict__ W,
                                             float* Wh, float* Wl, int t) {
    #pragma unroll
    for (int i = 0; i < 16; i++) {
        int e4 = i * 256 + t;
        int e  = e4 * 4;
        int k  = e >> 7;
        int n  = e & 127;
        float4 w = __ldg((const float4*)&W[e]);
        float4 h4, l4;
        split_tf32(w.x, h4.x, l4.x);
        split_tf32(w.y, h4.y, l4.y);
        split_tf32(w.z, h4.z, l4.z);
        split_tf32(w.w, h4.w, l4.w);
        *(float4*)&Wh[k * SB + n] = h4;
        *(float4*)&Wl[k * SB + n] = l4;
    }
}

__global__ void __launch_bounds__(256, 1)
k_mlp(const float* __restrict__ W1, const float* __restrict__ B1,
      const float* __restrict__ W2, const float* __restrict__ B2,
      int outsel) {
    extern __shared__ float sm[];
    float* As = sm;                    // [128][SA]  Z tile, later reused as relu(T) tile
    float* Wh = sm + 128 * SA;         // [128][SB]  weight hi
    float* Wl = Wh + 128 * SB;         // [128][SB]  weight lo

    float* hout = (outsel == 1) ? g_hA : g_hB;

    const int t    = threadIdx.x;
    const int wid  = t >> 5;
    const int lane = t & 31;
    const int wm   = wid & 3;    // warp row group: rows wm*32 .. +31
    const int wn   = wid >> 2;   // warp col group: cols wn*64 .. +63
    const int grp  = lane >> 2;  // 0..7
    const int qid  = lane & 3;   // 0..3
    const int row0 = blockIdx.x * 128;

    // ---- stage Z tile (fp32) + W1 (split) ----
    #pragma unroll
    for (int i = 0; i < 16; i++) {
        int e4 = i * 256 + t;
        int e  = e4 * 4;
        int r  = e >> 7;
        int k  = e & 127;
        int row = row0 + r;
        float4 v = make_float4(0.f, 0.f, 0.f, 0.f);
        if (row < NN) v = __ldg((const float4*)&g_z[row * 128 + k]);
        *(float4*)&As[r * SA + k] = v;
    }
    load_w_split(W1, Wh, Wl, t);
    __syncthreads();

    float acc[2][8][4];
    #pragma unroll
    for (int mt = 0; mt < 2; mt++)
        #pragma unroll
        for (int nt = 0; nt < 8; nt++)
            #pragma unroll
            for (int q = 0; q < 4; q++) acc[mt][nt][q] = 0.f;

    // ---- GEMM 1 ----
    #pragma unroll 4
    for (int kk = 0; kk < 16; kk++) {
        int k0 = kk * 8;
        unsigned ah[2][4], al[2][4];
        #pragma unroll
        for (int mt = 0; mt < 2; mt++) {
            int rb = wm * 32 + mt * 16;
            float x0 = As[(rb + grp) * SA + k0 + qid];
            float x1 = As[(rb + grp + 8) * SA + k0 + qid];
            float x2 = As[(rb + grp) * SA + k0 + qid + 4];
            float x3 = As[(rb + grp + 8) * SA + k0 + qid + 4];
            float h, l;
            split_tf32(x0, h, l); ah[mt][0] = __float_as_uint(h); al[mt][0] = __float_as_uint(l);
            split_tf32(x1, h, l); ah[mt][1] = __float_as_uint(h); al[mt][1] = __float_as_uint(l);
            split_tf32(x2, h, l); ah[mt][2] = __float_as_uint(h); al[mt][2] = __float_as_uint(l);
            split_tf32(x3, h, l); ah[mt][3] = __float_as_uint(h); al[mt][3] = __float_as_uint(l);
        }
        #pragma unroll
        for (int nt = 0; nt < 8; nt++) {
            int cb = wn * 64 + nt * 8;
            unsigned bh[2], bl[2];
            bh[0] = __float_as_uint(Wh[(k0 + qid) * SB + cb + grp]);
            bh[1] = __float_as_uint(Wh[(k0 + qid + 4) * SB + cb + grp]);
            bl[0] = __float_as_uint(Wl[(k0 + qid) * SB + cb + grp]);
            bl[1] = __float_as_uint(Wl[(k0 + qid + 4) * SB + cb + grp]);
            #pragma unroll
            for (int mt = 0; mt < 2; mt++) {
                mma_tf32(acc[mt][nt], ah[mt], bh);
                mma_tf32(acc[mt][nt], al[mt], bh);
                mma_tf32(acc[mt][nt], ah[mt], bl);
            }
        }
    }

    __syncthreads();   // everyone done reading As (Z) and Wh/Wl (W1)

    // ---- epilogue 1: relu(acc + b1) -> As (as [m][k] for GEMM2); load W2 split ----
    #pragma unroll
    for (int mt = 0; mt < 2; mt++) {
        int r0 = wm * 32 + mt * 16 + grp;
        #pragma unroll
        for (int nt = 0; nt < 8; nt++) {
            int c = wn * 64 + nt * 8 + qid * 2;
            float b0 = __ldg(&B1[c]);
            float b1v = __ldg(&B1[c + 1]);
            float2 v0 = make_float2(fmaxf(acc[mt][nt][0] + b0, 0.f),
                                    fmaxf(acc[mt][nt][1] + b1v, 0.f));
            float2 v1 = make_float2(fmaxf(acc[mt][nt][2] + b0, 0.f),
                                    fmaxf(acc[mt][nt][3] + b1v, 0.f));
            *(float2*)&As[r0 * SA + c]       = v0;
            *(float2*)&As[(r0 + 8) * SA + c] = v1;
        }
    }
    load_w_split(W2, Wh, Wl, t);
    __syncthreads();

    #pragma unroll
    for (int mt = 0; mt < 2; mt++)
        #pragma unroll
        for (int nt = 0; nt < 8; nt++)
            #pragma unroll
            for (int q = 0; q < 4; q++) acc[mt][nt][q] = 0.f;

    // ---- GEMM 2 ----
    #pragma unroll 4
    for (int kk = 0; kk < 16; kk++) {
        int k0 = kk * 8;
        unsigned ah[2][4], al[2][4];
        #pragma unroll
        for (int mt = 0; mt < 2; mt++) {
            int rb = wm * 32 + mt * 16;
            float x0 = As[(rb + grp) * SA + k0 + qid];
            float x1 = As[(rb + grp + 8) * SA + k0 + qid];
            float x2 = As[(rb + grp) * SA + k0 + qid + 4];
            float x3 = As[(rb + grp + 8) * SA + k0 + qid + 4];
            float h, l;
            split_tf32(x0, h, l); ah[mt][0] = __float_as_uint(h); al[mt][0] = __float_as_uint(l);
            split_tf32(x1, h, l); ah[mt][1] = __float_as_uint(h); al[mt][1] = __float_as_uint(l);
            split_tf32(x2, h, l); ah[mt][2] = __float_as_uint(h); al[mt][2] = __float_as_uint(l);
            split_tf32(x3, h, l); ah[mt][3] = __float_as_uint(h); al[mt][3] = __float_as_uint(l);
        }
        #pragma unroll
        for (int nt = 0; nt < 8; nt++) {
            int cb = wn * 64 + nt * 8;
            unsigned bh[2], bl[2];
            bh[0] = __float_as_uint(Wh[(k0 + qid) * SB + cb + grp]);
            bh[1] = __float_as_uint(Wh[(k0 + qid + 4) * SB + cb + grp]);
            bl[0] = __float_as_uint(Wl[(k0 + qid) * SB + cb + grp]);
            bl[1] = __float_as_uint(Wl[(k0 + qid + 4) * SB + cb + grp]);
            #pragma unroll
            for (int mt = 0; mt < 2; mt++) {
                mma_tf32(acc[mt][nt], ah[mt], bh);
                mma_tf32(acc[mt][nt], al[mt], bh);
                mma_tf32(acc[mt][nt], ah[mt], bl);
            }
        }
    }

    // ---- epilogue 2: acc + b2 -> global ----
    #pragma unroll
    for (int mt = 0; mt < 2; mt++) {
        int r0 = row0 + wm * 32 + mt * 16 + grp;
        #pragma unroll
        for (int nt = 0; nt < 8; nt++) {
            int c = wn * 64 + nt * 8 + qid * 2;
            float b0 = __ldg(&B2[c]);
            float b1v = __ldg(&B2[c + 1]);
            if (r0 < NN)
                *(float2*)&hout[r0 * 128 + c] =
                    make_float2(acc[mt][nt][0] + b0, acc[mt][nt][1] + b1v);
            if (r0 + 8 < NN)
                *(float2*)&hout[(r0 + 8) * 128 + c] =
                    make_float2(acc[mt][nt][2] + b0, acc[mt][nt][3] + b1v);
        }
    }
}

// ---------------- graph sum pooling ----------------
__global__ void k_zero_out(float* __restrict__ out) {
    int i = blockIdx.x * blockDim.x + threadIdx.x;
    if (i < NG * D) out[i] = 0.f;
}

__global__ void k_pool(const int* __restrict__ gid, float* __restrict__ out) {
    int c  = threadIdx.x;
    int n0 = blockIdx.x * 128;
    float acc = 0.f;
    int cur = -1;
    for (int r = 0; r < 128; r++) {
        int n = n0 + r;
        if (n >= NN) break;
        int g = __ldg(&gid[n]);
        if (g != cur) {
            if (cur >= 0) atomicAdd(&out[cur * 128 + c], acc);
            cur = g;
            acc = 0.f;
        }
        acc += g_hA[n * 128 + c];
    }
    if (cur >= 0) atomicAdd(&out[cur * 128 + c], acc);
}

// ---------------- launch ----------------
extern "C" void kernel_launch(void* const* d_in, const int* in_sizes, int n_in,
                              void* d_out, int out_size) {
    const float* feats = (const float*)d_in[0];
    const int*   esrc  = (const int*)d_in[1];
    const int*   edst  = (const int*)d_in[2];
    const int*   gid   = (const int*)d_in[3];
    const float* eps   = (const float*)d_in[4];
    const float* W1[3] = {(const float*)d_in[5],  (const float*)d_in[9],  (const float*)d_in[13]};
    const float* B1[3] = {(const float*)d_in[6],  (const float*)d_in[10], (const float*)d_in[14]};
    const float* W2[3] = {(const float*)d_in[7],  (const float*)d_in[11], (const float*)d_in[15]};
    const float* B2[3] = {(const float*)d_in[8],  (const float*)d_in[12], (const float*)d_in[16]};
    float* out = (float*)d_out;
    (void)in_sizes; (void)n_in; (void)out_size;

    cudaFuncSetAttribute(k_mlp, cudaFuncAttributeMaxDynamicSharedMemorySize, MLP_SMEM);

    k_zero_cnt<<<(NN + 255) / 256, 256>>>();
    k_count<<<(NE + 255) / 256, 256>>>(edst);
    k_scan<<<1, 1024>>>();
    k_scatter<<<(NE + 255) / 256, 256>>>(esrc, edst);

    int aggGrid = (NN * 32 + 255) / 256;
    int mlpGrid = (NN + 127) / 128;

    k_agg<<<aggGrid, 256>>>(feats, eps, 0, 0);
    k_mlp<<<mlpGrid, 256, MLP_SMEM>>>(W1[0], B1[0], W2[0], B2[0], 1);
    k_agg<<<aggGrid, 256>>>(feats, eps, 1, 1);
    k_mlp<<<mlpGrid, 256, MLP_SMEM>>>(W1[1], B1[1], W2[1], B2[1], 2);
    k_agg<<<aggGrid, 256>>>(feats, eps, 2, 2);
    k_mlp<<<mlpGrid, 256, MLP_SMEM>>>(W1[2], B1[2], W2[2], B2[2], 1);

    k_zero_out<<<(NG * D + 255) / 256, 256>>>(out);
    k_pool<<<(NN + 127) / 128, 128>>>(gid, out);
}

// round 3
// speedup vs baseline: 1.3467x; 1.1706x over previous
#include <cuda_runtime.h>

#define NN 50000
#define NE 800000
#define D  128
#define NG 128

// ---------------- device scratch ----------------
__device__ float g_hA[NN * D];
__device__ float g_hB[NN * D];
__device__ int   g_rowptr[NN + 1];
__device__ int   g_pos[NN];
__device__ int   g_cnt[NN];
__device__ int   g_col[NE];
__device__ int   g_bsum[128];
__device__ int   g_boff[128];

#define SCAN_B 98   // ceil(50000/512)

// ---------------- CSR build ----------------
__global__ void k_zero_cnt() {
    int i = blockIdx.x * blockDim.x + threadIdx.x;
    if (i < NN) g_cnt[i] = 0;
}

__global__ void k_count(const int* __restrict__ dst) {
    int e = blockIdx.x * blockDim.x + threadIdx.x;
    if (e < NE) atomicAdd(&g_cnt[dst[e]], 1);
}

// pass 1: per-block local exclusive scan + block sums
__global__ void k_scan1() {
    int t = threadIdx.x, b = blockIdx.x;
    int i = b * 512 + t;
    int v = (i < NN) ? g_cnt[i] : 0;
    int x = v;
    #pragma unroll
    for (int o = 1; o < 32; o <<= 1) {
        int y = __shfl_up_sync(0xffffffffu, x, o);
        if ((t & 31) >= o) x += y;
    }
    __shared__ int ws[16];
    if ((t & 31) == 31) ws[t >> 5] = x;
    __syncthreads();
    if (t < 16) {
        int y = ws[t];
        #pragma unroll
        for (int o = 1; o < 16; o <<= 1) {
            int z = __shfl_up_sync(0xffffu, y, o);
            if (t >= o) y += z;
        }
        ws[t] = y;
    }
    __syncthreads();
    int off = (t >= 32) ? ws[(t >> 5) - 1] : 0;
    int incl = x + off;
    if (i < NN) g_pos[i] = incl - v;     // local exclusive
    if (t == 511) g_bsum[b] = incl;      // block total
}

// pass 2: scan block sums (1 block, 128 threads)
__global__ void k_scan2() {
    int t = threadIdx.x;
    int v = (t < SCAN_B) ? g_bsum[t] : 0;
    int x = v;
    #pragma unroll
    for (int o = 1; o < 32; o <<= 1) {
        int y = __shfl_up_sync(0xffffffffu, x, o);
        if ((t & 31) >= o) x += y;
    }
    __shared__ int ws[4];
    if ((t & 31) == 31) ws[t >> 5] = x;
    __syncthreads();
    if (t < 4) {
        int y = ws[t];
        #pragma unroll
        for (int o = 1; o < 4; o <<= 1) {
            int z = __shfl_up_sync(0xfu, y, o);
            if (t >= o) y += z;
        }
        ws[t] = y;
    }
    __syncthreads();
    int off = (t >= 32) ? ws[(t >> 5) - 1] : 0;
    g_boff[t] = x + off - v;             // global exclusive block offset
}

// pass 3: add offsets, emit rowptr + pos
__global__ void k_scan3() {
    int t = threadIdx.x, b = blockIdx.x;
    int i = b * 512 + t;
    if (i < NN) {
        int p = g_pos[i] + g_boff[b];
        g_pos[i] = p;
        g_rowptr[i] = p;
    }
    if (b == 0 && t == 0) g_rowptr[NN] = NE;
}

__global__ void k_scatter(const int* __restrict__ src, const int* __restrict__ dst) {
    int e = blockIdx.x * blockDim.x + threadIdx.x;
    if (e < NE) {
        int d = dst[e];
        int p = atomicAdd(&g_pos[d], 1);
        g_col[p] = src[e];
    }
}

// ---------------- fused layer: gather + 2xGEMM (3xTF32) + (pool) ----------------
#define SA 132
#define SB 136
#define MLP_SMEM ((128 * SA + 2 * 128 * SB) * 4)   // 206848 B

__device__ __forceinline__ void mma_tf32(float* c, const unsigned* a, const unsigned* b) {
    asm volatile("mma.sync.aligned.m16n8k8.row.col.f32.tf32.tf32.f32 "
        "{%0,%1,%2,%3}, {%4,%5,%6,%7}, {%8,%9}, {%0,%1,%2,%3};"
        : "+f"(c[0]), "+f"(c[1]), "+f"(c[2]), "+f"(c[3])
        : "r"(a[0]), "r"(a[1]), "r"(a[2]), "r"(a[3]), "r"(b[0]), "r"(b[1]));
}

__device__ __forceinline__ void split_tf32(float x, float& hi, float& lo) {
    unsigned h;
    asm("cvt.rna.tf32.f32 %0, %1;" : "=r"(h) : "f"(x));
    hi = __uint_as_float(h);
    float lf = x - hi;
    unsigned l;
    asm("cvt.rna.tf32.f32 %0, %1;" : "=r"(l) : "f"(lf));
    lo = __uint_as_float(l);
}

__device__ __forceinline__ void load_w_split512(const float* __restrict__ W,
                                                float* Wh, float* Wl, int t) {
    #pragma unroll
    for (int i = 0; i < 8; i++) {
        int e = (i * 512 + t) * 4;
        int k = e >> 7;
        int n = e & 127;
        float4 w = __ldg((const float4*)&W[e]);
        float4 h4, l4;
        split_tf32(w.x, h4.x, l4.x);
        split_tf32(w.y, h4.y, l4.y);
        split_tf32(w.z, h4.z, l4.z);
        split_tf32(w.w, h4.w, l4.w);
        *(float4*)&Wh[k * SB + n] = h4;
        *(float4*)&Wl[k * SB + n] = l4;
    }
}

__global__ void __launch_bounds__(512, 1)
k_layer(const float* __restrict__ hin, const float* __restrict__ eps, int layer,
        const float* __restrict__ W1, const float* __restrict__ B1,
        const float* __restrict__ W2, const float* __restrict__ B2,
        float* __restrict__ hout,
        const int* __restrict__ gid, float* __restrict__ out) {
    extern __shared__ float sm[];
    float* As = sm;                    // [128][SA] z tile -> relu tile -> out tile
    float* Wh = sm + 128 * SA;
    float* Wl = Wh + 128 * SB;

    const int t    = threadIdx.x;
    const int wid  = t >> 5;
    const int lane = t & 31;
    const int wm   = wid & 3;          // rows wm*32..+31
    const int wn   = wid >> 2;         // cols wn*32..+31
    const int grp  = lane >> 2;
    const int qid  = lane & 3;
    const int row0 = blockIdx.x * 128;

    // ---- gather: z = (1+eps)*h + sum_neighbors, straight into smem ----
    {
        const float4* hv = (const float4*)hin;
        float ev = 1.0f + __ldg(&eps[layer]);
        #pragma unroll
        for (int i = 0; i < 8; i++) {
            int r = wid * 8 + i;
            int node = row0 + r;
            float4 a = make_float4(0.f, 0.f, 0.f, 0.f);
            if (node < NN) {
                a = __ldg(&hv[node * 32 + lane]);
                a.x *= ev; a.y *= ev; a.z *= ev; a.w *= ev;
                int jb = g_rowptr[node];
                int je = g_rowptr[node + 1];
                int j = jb;
                for (; j + 4 <= je; j += 4) {
                    int s0 = g_col[j], s1 = g_col[j + 1], s2 = g_col[j + 2], s3 = g_col[j + 3];
                    float4 x0 = __ldg(&hv[s0 * 32 + lane]);
                    float4 x1 = __ldg(&hv[s1 * 32 + lane]);
                    float4 x2 = __ldg(&hv[s2 * 32 + lane]);
                    float4 x3 = __ldg(&hv[s3 * 32 + lane]);
                    a.x += x0.x + x1.x + x2.x + x3.x;
                    a.y += x0.y + x1.y + x2.y + x3.y;
                    a.z += x0.z + x1.z + x2.z + x3.z;
                    a.w += x0.w + x1.w + x2.w + x3.w;
                }
                for (; j < je; j++) {
                    int s = g_col[j];
                    float4 x = __ldg(&hv[s * 32 + lane]);
                    a.x += x.x; a.y += x.y; a.z += x.z; a.w += x.w;
                }
            }
            *(float4*)&As[r * SA + lane * 4] = a;
        }
    }
    load_w_split512(W1, Wh, Wl, t);
    __syncthreads();

    float acc[2][4][4];
    #pragma unroll
    for (int mt = 0; mt < 2; mt++)
        #pragma unroll
        for (int nt = 0; nt < 4; nt++)
            #pragma unroll
            for (int q = 0; q < 4; q++) acc[mt][nt][q] = 0.f;

    // ---- GEMM 1 ----
    #pragma unroll 4
    for (int kk = 0; kk < 16; kk++) {
        int k0 = kk * 8;
        unsigned ah[2][4], al[2][4];
        #pragma unroll
        for (int mt = 0; mt < 2; mt++) {
            int rb = wm * 32 + mt * 16;
            float x0 = As[(rb + grp) * SA + k0 + qid];
            float x1 = As[(rb + grp + 8) * SA + k0 + qid];
            float x2 = As[(rb + grp) * SA + k0 + qid + 4];
            float x3 = As[(rb + grp + 8) * SA + k0 + qid + 4];
            float h, l;
            split_tf32(x0, h, l); ah[mt][0] = __float_as_uint(h); al[mt][0] = __float_as_uint(l);
            split_tf32(x1, h, l); ah[mt][1] = __float_as_uint(h); al[mt][1] = __float_as_uint(l);
            split_tf32(x2, h, l); ah[mt][2] = __float_as_uint(h); al[mt][2] = __float_as_uint(l);
            split_tf32(x3, h, l); ah[mt][3] = __float_as_uint(h); al[mt][3] = __float_as_uint(l);
        }
        #pragma unroll
        for (int nt = 0; nt < 4; nt++) {
            int cb = wn * 32 + nt * 8;
            unsigned bh[2], bl[2];
            bh[0] = __float_as_uint(Wh[(k0 + qid) * SB + cb + grp]);
            bh[1] = __float_as_uint(Wh[(k0 + qid + 4) * SB + cb + grp]);
            bl[0] = __float_as_uint(Wl[(k0 + qid) * SB + cb + grp]);
            bl[1] = __float_as_uint(Wl[(k0 + qid + 4) * SB + cb + grp]);
            #pragma unroll
            for (int mt = 0; mt < 2; mt++) {
                mma_tf32(acc[mt][nt], ah[mt], bh);
                mma_tf32(acc[mt][nt], al[mt], bh);
                mma_tf32(acc[mt][nt], ah[mt], bl);
            }
        }
    }

    __syncthreads();

    // ---- epilogue 1: relu -> As; stage W2 ----
    #pragma unroll
    for (int mt = 0; mt < 2; mt++) {
        int r0 = wm * 32 + mt * 16 + grp;
        #pragma unroll
        for (int nt = 0; nt < 4; nt++) {
            int c = wn * 32 + nt * 8 + qid * 2;
            float b0 = __ldg(&B1[c]);
            float b1v = __ldg(&B1[c + 1]);
            *(float2*)&As[r0 * SA + c] =
                make_float2(fmaxf(acc[mt][nt][0] + b0, 0.f), fmaxf(acc[mt][nt][1] + b1v, 0.f));
            *(float2*)&As[(r0 + 8) * SA + c] =
                make_float2(fmaxf(acc[mt][nt][2] + b0, 0.f), fmaxf(acc[mt][nt][3] + b1v, 0.f));
        }
    }
    load_w_split512(W2, Wh, Wl, t);
    __syncthreads();

    #pragma unroll
    for (int mt = 0; mt < 2; mt++)
        #pragma unroll
        for (int nt = 0; nt < 4; nt++)
            #pragma unroll
            for (int q = 0; q < 4; q++) acc[mt][nt][q] = 0.f;

    // ---- GEMM 2 ----
    #pragma unroll 4
    for (int kk = 0; kk < 16; kk++) {
        int k0 = kk * 8;
        unsigned ah[2][4], al[2][4];
        #pragma unroll
        for (int mt = 0; mt < 2; mt++) {
            int rb = wm * 32 + mt * 16;
            float x0 = As[(rb + grp) * SA + k0 + qid];
            float x1 = As[(rb + grp + 8) * SA + k0 + qid];
            float x2 = As[(rb + grp) * SA + k0 + qid + 4];
            float x3 = As[(rb + grp + 8) * SA + k0 + qid + 4];
            float h, l;
            split_tf32(x0, h, l); ah[mt][0] = __float_as_uint(h); al[mt][0] = __float_as_uint(l);
            split_tf32(x1, h, l); ah[mt][1] = __float_as_uint(h); al[mt][1] = __float_as_uint(l);
            split_tf32(x2, h, l); ah[mt][2] = __float_as_uint(h); al[mt][2] = __float_as_uint(l);
            split_tf32(x3, h, l); ah[mt][3] = __float_as_uint(h); al[mt][3] = __float_as_uint(l);
        }
        #pragma unroll
        for (int nt = 0; nt < 4; nt++) {
            int cb = wn * 32 + nt * 8;
            unsigned bh[2], bl[2];
            bh[0] = __float_as_uint(Wh[(k0 + qid) * SB + cb + grp]);
            bh[1] = __float_as_uint(Wh[(k0 + qid + 4) * SB + cb + grp]);
            bl[0] = __float_as_uint(Wl[(k0 + qid) * SB + cb + grp]);
            bl[1] = __float_as_uint(Wl[(k0 + qid + 4) * SB + cb + grp]);
            #pragma unroll
            for (int mt = 0; mt < 2; mt++) {
                mma_tf32(acc[mt][nt], ah[mt], bh);
                mma_tf32(acc[mt][nt], al[mt], bh);
                mma_tf32(acc[mt][nt], ah[mt], bl);
            }
        }
    }

    // ---- epilogue 2 ----
    if (hout) {
        #pragma unroll
        for (int mt = 0; mt < 2; mt++) {
            int r0 = row0 + wm * 32 + mt * 16 + grp;
            #pragma unroll
            for (int nt = 0; nt < 4; nt++) {
                int c = wn * 32 + nt * 8 + qid * 2;
                float b0 = __ldg(&B2[c]);
                float b1v = __ldg(&B2[c + 1]);
                if (r0 < NN)
                    *(float2*)&hout[r0 * 128 + c] =
                        make_float2(acc[mt][nt][0] + b0, acc[mt][nt][1] + b1v);
                if (r0 + 8 < NN)
                    *(float2*)&hout[(r0 + 8) * 128 + c] =
                        make_float2(acc[mt][nt][2] + b0, acc[mt][nt][3] + b1v);
            }
        }
    } else {
        // final layer: stage tile in smem, then run-length pooled atomics
        __syncthreads();   // all warps done reading As (GEMM2)
        #pragma unroll
        for (int mt = 0; mt < 2; mt++) {
            int r0 = wm * 32 + mt * 16 + grp;
            #pragma unroll
            for (int nt = 0; nt < 4; nt++) {
                int c = wn * 32 + nt * 8 + qid * 2;
                float b0 = __ldg(&B2[c]);
                float b1v = __ldg(&B2[c + 1]);
                *(float2*)&As[r0 * SA + c] =
                    make_float2(acc[mt][nt][0] + b0, acc[mt][nt][1] + b1v);
                *(float2*)&As[(r0 + 8) * SA + c] =
                    make_float2(acc[mt][nt][2] + b0, acc[mt][nt][3] + b1v);
            }
        }
        __syncthreads();
        int gg = t >> 7;        // 0..3 -> rows gg*32..+31
        int c  = t & 127;
        float pacc = 0.f;
        int cur = -1;
        for (int r = gg * 32; r < gg * 32 + 32; r++) {
            int node = row0 + r;
            if (node >= NN) break;
            int g = __ldg(&gid[node]);
            if (g != cur) {
                if (cur >= 0) atomicAdd(&out[cur * 128 + c], pacc);
                cur = g;
                pacc = 0.f;
            }
            pacc += As[r * SA + c];
        }
        if (cur >= 0) atomicAdd(&out[cur * 128 + c], pacc);
    }
}

// ---------------- misc ----------------
__global__ void k_zero_out(float* __restrict__ out) {
    int i = blockIdx.x * blockDim.x + threadIdx.x;
    if (i < NG * D) out[i] = 0.f;
}

// ---------------- launch ----------------
extern "C" void kernel_launch(void* const* d_in, const int* in_sizes, int n_in,
                              void* d_out, int out_size) {
    const float* feats = (const float*)d_in[0];
    const int*   esrc  = (const int*)d_in[1];
    const int*   edst  = (const int*)d_in[2];
    const int*   gid   = (const int*)d_in[3];
    const float* eps   = (const float*)d_in[4];
    const float* W1[3] = {(const float*)d_in[5],  (const float*)d_in[9],  (const float*)d_in[13]};
    const float* B1[3] = {(const float*)d_in[6],  (const float*)d_in[10], (const float*)d_in[14]};
    const float* W2[3] = {(const float*)d_in[7],  (const float*)d_in[11], (const float*)d_in[15]};
    const float* B2[3] = {(const float*)d_in[8],  (const float*)d_in[12], (const float*)d_in[16]};
    float* out = (float*)d_out;
    (void)in_sizes; (void)n_in; (void)out_size;

    cudaFuncSetAttribute(k_layer, cudaFuncAttributeMaxDynamicSharedMemorySize, MLP_SMEM);

    float* hA; cudaGetSymbolAddress((void**)&hA, g_hA);
    float* hB; cudaGetSymbolAddress((void**)&hB, g_hB);

    // CSR build
    k_zero_cnt<<<(NN + 255) / 256, 256>>>();
    k_count<<<(NE + 255) / 256, 256>>>(edst);
    k_scan1<<<SCAN_B, 512>>>();
    k_scan2<<<1, 128>>>();
    k_scan3<<<SCAN_B, 512>>>();
    k_scatter<<<(NE + 255) / 256, 256>>>(esrc, edst);
    k_zero_out<<<(NG * D + 255) / 256, 256>>>(out);

    int grid = (NN + 127) / 128;
    k_layer<<<grid, 512, MLP_SMEM>>>(feats, eps, 0, W1[0], B1[0], W2[0], B2[0], hA, gid, out);
    k_layer<<<grid, 512, MLP_SMEM>>>(hA,    eps, 1, W1[1], B1[1], W2[1], B2[1], hB, gid, out);
    k_layer<<<grid, 512, MLP_SMEM>>>(hB,    eps, 2, W1[2], B1[2], W2[2], B2[2], nullptr, gid, out);
}

// round 4
// speedup vs baseline: 1.6575x; 1.2308x over previous
#include <cuda_runtime.h>
#include <cuda_bf16.h>

#define NN 50000
#define NE 800000
#define D  128
#define NG 128

#define SA 132   // As row stride (floats)
#define SW 136   // W row stride (bf16), n-major [n=128][k=128+pad]

// ---------------- device scratch ----------------
__device__ float g_hA[NN * D];
__device__ float g_hB[NN * D];
__device__ int   g_rowptr[NN + 1];
__device__ int   g_pos[NN];
__device__ int   g_cnt[NN];
__device__ int   g_col[NE];
__device__ int   g_bsum[128];
__device__ int   g_boff[128];
// [layer][W1/W2][hi/lo][n*SW+k]
__device__ __nv_bfloat16 g_wsplit[3][2][2][128 * SW];

#define SCAN_B 98

// ---------------- CSR build ----------------
__global__ void k_zero_cnt() {
    int i = blockIdx.x * blockDim.x + threadIdx.x;
    if (i < NN) g_cnt[i] = 0;
}

__global__ void k_count(const int* __restrict__ dst) {
    int e = blockIdx.x * blockDim.x + threadIdx.x;
    if (e < NE) atomicAdd(&g_cnt[dst[e]], 1);
}

__global__ void k_scan1() {
    int t = threadIdx.x, b = blockIdx.x;
    int i = b * 512 + t;
    int v = (i < NN) ? g_cnt[i] : 0;
    int x = v;
    #pragma unroll
    for (int o = 1; o < 32; o <<= 1) {
        int y = __shfl_up_sync(0xffffffffu, x, o);
        if ((t & 31) >= o) x += y;
    }
    __shared__ int ws[16];
    if ((t & 31) == 31) ws[t >> 5] = x;
    __syncthreads();
    if (t < 16) {
        int y = ws[t];
        #pragma unroll
        for (int o = 1; o < 16; o <<= 1) {
            int z = __shfl_up_sync(0xffffu, y, o);
            if (t >= o) y += z;
        }
        ws[t] = y;
    }
    __syncthreads();
    int off = (t >= 32) ? ws[(t >> 5) - 1] : 0;
    int incl = x + off;
    if (i < NN) g_pos[i] = incl - v;
    if (t == 511) g_bsum[b] = incl;
}

__global__ void k_scan2() {
    int t = threadIdx.x;
    int v = (t < SCAN_B) ? g_bsum[t] : 0;
    int x = v;
    #pragma unroll
    for (int o = 1; o < 32; o <<= 1) {
        int y = __shfl_up_sync(0xffffffffu, x, o);
        if ((t & 31) >= o) x += y;
    }
    __shared__ int ws[4];
    if ((t & 31) == 31) ws[t >> 5] = x;
    __syncthreads();
    if (t < 4) {
        int y = ws[t];
        #pragma unroll
        for (int o = 1; o < 4; o <<= 1) {
            int z = __shfl_up_sync(0xfu, y, o);
            if (t >= o) y += z;
        }
        ws[t] = y;
    }
    __syncthreads();
    int off = (t >= 32) ? ws[(t >> 5) - 1] : 0;
    g_boff[t] = x + off - v;
}

__global__ void k_scan3() {
    int t = threadIdx.x, b = blockIdx.x;
    int i = b * 512 + t;
    if (i < NN) {
        int p = g_pos[i] + g_boff[b];
        g_pos[i] = p;
        g_rowptr[i] = p;
    }
    if (b == 0 && t == 0) g_rowptr[NN] = NE;
}

__global__ void k_scatter(const int* __restrict__ src, const int* __restrict__ dst) {
    int e = blockIdx.x * blockDim.x + threadIdx.x;
    if (e < NE) {
        int d = dst[e];
        int p = atomicAdd(&g_pos[d], 1);
        g_col[p] = src[e];
    }
}

// ---------------- weight pre-split: fp32 [k][n] -> bf16 hi/lo, n-major [n][SW] ----------------
__global__ void k_prep(const float* __restrict__ W, int layer, int which) {
    int t = blockIdx.x * 256 + threadIdx.x;
    if (t >= 128 * 128) return;
    int n = t >> 7;
    int k = t & 127;
    float x = __ldg(&W[k * 128 + n]);
    __nv_bfloat16 h = __float2bfloat16_rn(x);
    float lo = x - __bfloat162float(h);
    g_wsplit[layer][which][0][n * SW + k] = h;
    g_wsplit[layer][which][1][n * SW + k] = __float2bfloat16_rn(lo);
}

// ---------------- fused layer ----------------
#define LAYER_SMEM ((64 * SA) * 4 + 2 * 128 * SW * 2)   // 33792 + 69632 = 103424

__device__ __forceinline__ void mma_bf16(float* c, const unsigned* a, const unsigned* b) {
    asm volatile("mma.sync.aligned.m16n8k16.row.col.f32.bf16.bf16.f32 "
        "{%0,%1,%2,%3}, {%4,%5,%6,%7}, {%8,%9}, {%0,%1,%2,%3};"
        : "+f"(c[0]), "+f"(c[1]), "+f"(c[2]), "+f"(c[3])
        : "r"(a[0]), "r"(a[1]), "r"(a[2]), "r"(a[3]), "r"(b[0]), "r"(b[1]));
}

// split float2 into bf16x2 hi (returned) and bf16x2 lo (out param)
__device__ __forceinline__ unsigned sp2(float2 x, unsigned& lo) {
    __nv_bfloat162 h = __float22bfloat162_rn(x);
    unsigned hu = *reinterpret_cast<unsigned*>(&h);
    float hx = __uint_as_float(hu << 16);
    float hy = __uint_as_float(hu & 0xffff0000u);
    __nv_bfloat162 l = __float22bfloat162_rn(make_float2(x.x - hx, x.y - hy));
    lo = *reinterpret_cast<unsigned*>(&l);
    return hu;
}

__device__ __forceinline__ void copy_w(const __nv_bfloat16* __restrict__ sh,
                                       const __nv_bfloat16* __restrict__ sl,
                                       __nv_bfloat16* dh, __nv_bfloat16* dl, int t) {
    const float4* s0 = (const float4*)sh;
    const float4* s1 = (const float4*)sl;
    float4* d0 = (float4*)dh;
    float4* d1 = (float4*)dl;
    #pragma unroll
    for (int i = t; i < 128 * SW * 2 / 16; i += 512) {
        d0[i] = __ldg(&s0[i]);
        d1[i] = __ldg(&s1[i]);
    }
}

__global__ void __launch_bounds__(512, 2)
k_layer(const float* __restrict__ hin, const float* __restrict__ eps, int layer,
        const float* __restrict__ B1, const float* __restrict__ B2,
        float* __restrict__ hout,
        const int* __restrict__ gid, float* __restrict__ out) {
    extern __shared__ float sm[];
    float* As = sm;                                        // [64][SA] fp32
    __nv_bfloat16* Wh = (__nv_bfloat16*)(sm + 64 * SA);    // [128][SW]
    __nv_bfloat16* Wl = Wh + 128 * SW;

    const int t    = threadIdx.x;
    const int wid  = t >> 5;
    const int lane = t & 31;
    const int wm   = wid & 1;      // rows wm*32..+31
    const int wn   = wid >> 1;     // cols wn*16..+15
    const int grp  = lane >> 2;
    const int qid  = lane & 3;
    const int row0 = blockIdx.x * 64;

    // ---- gather z into As; stage W1 hi/lo ----
    {
        const float4* hv = (const float4*)hin;
        float ev = 1.0f + __ldg(&eps[layer]);
        #pragma unroll
        for (int i = 0; i < 4; i++) {
            int r = wid * 4 + i;
            int node = row0 + r;
            float4 a = make_float4(0.f, 0.f, 0.f, 0.f);
            if (node < NN) {
                a = __ldg(&hv[node * 32 + lane]);
                a.x *= ev; a.y *= ev; a.z *= ev; a.w *= ev;
                int jb = g_rowptr[node];
                int je = g_rowptr[node + 1];
                int j = jb;
                for (; j + 4 <= je; j += 4) {
                    int s0 = g_col[j], s1 = g_col[j + 1], s2 = g_col[j + 2], s3 = g_col[j + 3];
                    float4 x0 = __ldg(&hv[s0 * 32 + lane]);
                    float4 x1 = __ldg(&hv[s1 * 32 + lane]);
                    float4 x2 = __ldg(&hv[s2 * 32 + lane]);
                    float4 x3 = __ldg(&hv[s3 * 32 + lane]);
                    a.x += x0.x + x1.x + x2.x + x3.x;
                    a.y += x0.y + x1.y + x2.y + x3.y;
                    a.z += x0.z + x1.z + x2.z + x3.z;
                    a.w += x0.w + x1.w + x2.w + x3.w;
                }
                for (; j < je; j++) {
                    int s = g_col[j];
                    float4 x = __ldg(&hv[s * 32 + lane]);
                    a.x += x.x; a.y += x.y; a.z += x.z; a.w += x.w;
                }
            }
            *(float4*)&As[r * SA + lane * 4] = a;
        }
    }
    copy_w(g_wsplit[layer][0][0], g_wsplit[layer][0][1], Wh, Wl, t);
    __syncthreads();

    float acc[2][2][4];
    #pragma unroll
    for (int mt = 0; mt < 2; mt++)
        #pragma unroll
        for (int nt = 0; nt < 2; nt++)
            #pragma unroll
            for (int q = 0; q < 4; q++) acc[mt][nt][q] = 0.f;

    // ---- GEMM 1 (bf16x2, 3 MMA terms) ----
    #pragma unroll 4
    for (int kk = 0; kk < 8; kk++) {
        int k0 = kk * 16;
        unsigned ah[2][4], al[2][4];
        #pragma unroll
        for (int mt = 0; mt < 2; mt++) {
            const float* p0 = &As[(wm * 32 + mt * 16 + grp) * SA + k0 + 2 * qid];
            const float* p1 = p0 + 8 * SA;
            ah[mt][0] = sp2(*(const float2*)p0,       al[mt][0]);
            ah[mt][1] = sp2(*(const float2*)p1,       al[mt][1]);
            ah[mt][2] = sp2(*(const float2*)(p0 + 8), al[mt][2]);
            ah[mt][3] = sp2(*(const float2*)(p1 + 8), al[mt][3]);
        }
        #pragma unroll
        for (int nt = 0; nt < 2; nt++) {
            int cb = wn * 16 + nt * 8;
            const __nv_bfloat16* wp = &Wh[(cb + grp) * SW + k0 + 2 * qid];
            const __nv_bfloat16* wq = &Wl[(cb + grp) * SW + k0 + 2 * qid];
            unsigned bh[2], bl[2];
            bh[0] = *(const unsigned*)wp;
            bh[1] = *(const unsigned*)(wp + 8);
            bl[0] = *(const unsigned*)wq;
            bl[1] = *(const unsigned*)(wq + 8);
            #pragma unroll
            for (int mt = 0; mt < 2; mt++) {
                mma_bf16(acc[mt][nt], ah[mt], bh);
                mma_bf16(acc[mt][nt], al[mt], bh);
                mma_bf16(acc[mt][nt], ah[mt], bl);
            }
        }
    }

    __syncthreads();

    // ---- epilogue 1: relu -> As; stage W2 ----
    #pragma unroll
    for (int mt = 0; mt < 2; mt++) {
        int r0 = wm * 32 + mt * 16 + grp;
        #pragma unroll
        for (int nt = 0; nt < 2; nt++) {
            int c = wn * 16 + nt * 8 + qid * 2;
            float b0 = __ldg(&B1[c]);
            float b1v = __ldg(&B1[c + 1]);
            *(float2*)&As[r0 * SA + c] =
                make_float2(fmaxf(acc[mt][nt][0] + b0, 0.f), fmaxf(acc[mt][nt][1] + b1v, 0.f));
            *(float2*)&As[(r0 + 8) * SA + c] =
                make_float2(fmaxf(acc[mt][nt][2] + b0, 0.f), fmaxf(acc[mt][nt][3] + b1v, 0.f));
        }
    }
    copy_w(g_wsplit[layer][1][0], g_wsplit[layer][1][1], Wh, Wl, t);
    __syncthreads();

    #pragma unroll
    for (int mt = 0; mt < 2; mt++)
        #pragma unroll
        for (int nt = 0; nt < 2; nt++)
            #pragma unroll
            for (int q = 0; q < 4; q++) acc[mt][nt][q] = 0.f;

    // ---- GEMM 2 ----
    #pragma unroll 4
    for (int kk = 0; kk < 8; kk++) {
        int k0 = kk * 16;
        unsigned ah[2][4], al[2][4];
        #pragma unroll
        for (int mt = 0; mt < 2; mt++) {
            const float* p0 = &As[(wm * 32 + mt * 16 + grp) * SA + k0 + 2 * qid];
            const float* p1 = p0 + 8 * SA;
            ah[mt][0] = sp2(*(const float2*)p0,       al[mt][0]);
            ah[mt][1] = sp2(*(const float2*)p1,       al[mt][1]);
            ah[mt][2] = sp2(*(const float2*)(p0 + 8), al[mt][2]);
            ah[mt][3] = sp2(*(const float2*)(p1 + 8), al[mt][3]);
        }
        #pragma unroll
        for (int nt = 0; nt < 2; nt++) {
            int cb = wn * 16 + nt * 8;
            const __nv_bfloat16* wp = &Wh[(cb + grp) * SW + k0 + 2 * qid];
            const __nv_bfloat16* wq = &Wl[(cb + grp) * SW + k0 + 2 * qid];
            unsigned bh[2], bl[2];
            bh[0] = *(const unsigned*)wp;
            bh[1] = *(const unsigned*)(wp + 8);
            bl[0] = *(const unsigned*)wq;
            bl[1] = *(const unsigned*)(wq + 8);
            #pragma unroll
            for (int mt = 0; mt < 2; mt++) {
                mma_bf16(acc[mt][nt], ah[mt], bh);
                mma_bf16(acc[mt][nt], al[mt], bh);
                mma_bf16(acc[mt][nt], ah[mt], bl);
            }
        }
    }

    // ---- epilogue 2 ----
    if (hout) {
        #pragma unroll
        for (int mt = 0; mt < 2; mt++) {
            int r0 = row0 + wm * 32 + mt * 16 + grp;
            #pragma unroll
            for (int nt = 0; nt < 2; nt++) {
                int c = wn * 16 + nt * 8 + qid * 2;
                float b0 = __ldg(&B2[c]);
                float b1v = __ldg(&B2[c + 1]);
                if (r0 < NN)
                    *(float2*)&hout[r0 * 128 + c] =
                        make_float2(acc[mt][nt][0] + b0, acc[mt][nt][1] + b1v);
                if (r0 + 8 < NN)
                    *(float2*)&hout[(r0 + 8) * 128 + c] =
                        make_float2(acc[mt][nt][2] + b0, acc[mt][nt][3] + b1v);
            }
        }
    } else {
        __syncthreads();
        #pragma unroll
        for (int mt = 0; mt < 2; mt++) {
            int r0 = wm * 32 + mt * 16 + grp;
            #pragma unroll
            for (int nt = 0; nt < 2; nt++) {
                int c = wn * 16 + nt * 8 + qid * 2;
                float b0 = __ldg(&B2[c]);
                float b1v = __ldg(&B2[c + 1]);
                *(float2*)&As[r0 * SA + c] =
                    make_float2(acc[mt][nt][0] + b0, acc[mt][nt][1] + b1v);
                *(float2*)&As[(r0 + 8) * SA + c] =
                    make_float2(acc[mt][nt][2] + b0, acc[mt][nt][3] + b1v);
            }
        }
        __syncthreads();
        int gg = t >> 7;       // 4 groups of 16 rows
        int c  = t & 127;
        float pacc = 0.f;
        int cur = -1;
        for (int r = gg * 16; r < gg * 16 + 16; r++) {
            int node = row0 + r;
            if (node >= NN) break;
            int g = __ldg(&gid[node]);
            if (g != cur) {
                if (cur >= 0) atomicAdd(&out[cur * 128 + c], pacc);
                cur = g;
                pacc = 0.f;
            }
            pacc += As[r * SA + c];
        }
        if (cur >= 0) atomicAdd(&out[cur * 128 + c], pacc);
    }
}

// ---------------- misc ----------------
__global__ void k_zero_out(float* __restrict__ out) {
    int i = blockIdx.x * blockDim.x + threadIdx.x;
    if (i < NG * D) out[i] = 0.f;
}

// ---------------- launch ----------------
extern "C" void kernel_launch(void* const* d_in, const int* in_sizes, int n_in,
                              void* d_out, int out_size) {
    const float* feats = (const float*)d_in[0];
    const int*   esrc  = (const int*)d_in[1];
    const int*   edst  = (const int*)d_in[2];
    const int*   gid   = (const int*)d_in[3];
    const float* eps   = (const float*)d_in[4];
    const float* W1[3] = {(const float*)d_in[5],  (const float*)d_in[9],  (const float*)d_in[13]};
    const float* B1[3] = {(const float*)d_in[6],  (const float*)d_in[10], (const float*)d_in[14]};
    const float* W2[3] = {(const float*)d_in[7],  (const float*)d_in[11], (const float*)d_in[15]};
    const float* B2[3] = {(const float*)d_in[8],  (const float*)d_in[12], (const float*)d_in[16]};
    float* out = (float*)d_out;
    (void)in_sizes; (void)n_in; (void)out_size;

    cudaFuncSetAttribute(k_layer, cudaFuncAttributeMaxDynamicSharedMemorySize, LAYER_SMEM);

    float* hA; cudaGetSymbolAddress((void**)&hA, g_hA);
    float* hB; cudaGetSymbolAddress((void**)&hB, g_hB);

    // weight pre-split
    for (int l = 0; l < 3; l++) {
        k_prep<<<64, 256>>>(W1[l], l, 0);
        k_prep<<<64, 256>>>(W2[l], l, 1);
    }

    // CSR build
    k_zero_cnt<<<(NN + 255) / 256, 256>>>();
    k_count<<<(NE + 255) / 256, 256>>>(edst);
    k_scan1<<<SCAN_B, 512>>>();
    k_scan2<<<1, 128>>>();
    k_scan3<<<SCAN_B, 512>>>();
    k_scatter<<<(NE + 255) / 256, 256>>>(esrc, edst);
    k_zero_out<<<(NG * D + 255) / 256, 256>>>(out);

    int grid = (NN + 63) / 64;
    k_layer<<<grid, 512, LAYER_SMEM>>>(feats, eps, 0, B1[0], B2[0], hA, gid, out);
    k_layer<<<grid, 512, LAYER_SMEM>>>(hA,    eps, 1, B1[1], B2[1], hB, gid, out);
    k_layer<<<grid, 512, LAYER_SMEM>>>(hB,    eps, 2, B1[2], B2[2], nullptr, gid, out);
}

// round 5
// speedup vs baseline: 1.9055x; 1.1496x over previous
#include <cuda_runtime.h>
#include <cuda_bf16.h>

#define NN 50000
#define NE 800000
#define D  128
#define NG 128

#define SA 132   // pool-staging row stride (floats)
#define SW 136   // bf16 row stride for A/W tiles

// ---------------- device scratch ----------------
__device__ float g_hA[NN * D];
__device__ float g_hB[NN * D];
__device__ int   g_rowptr[NN + 1];
__device__ int   g_pos[NN];
__device__ int   g_cnt[NN];
__device__ int   g_col[NE];
__device__ int   g_bsum[128];
__device__ int   g_boff[128];
// [layer][W1/W2][hi/lo][n*SW+k]
__device__ __nv_bfloat16 g_wsplit[3][2][2][128 * SW];

#define SCAN_B 98

// ---------------- init: zero cnt/out + split all 6 weights (one launch) ----------------
__global__ void k_init(const float* __restrict__ W10, const float* __restrict__ W20,
                       const float* __restrict__ W11, const float* __restrict__ W21,
                       const float* __restrict__ W12, const float* __restrict__ W22,
                       float* __restrict__ out) {
    int i = blockIdx.x * 256 + threadIdx.x;
    if (i < 6 * 16384) {
        int which = i >> 14;
        int rem = i & 16383;
        int n = rem >> 7, k = rem & 127;
        const float* W = (which == 0) ? W10 : (which == 1) ? W20 : (which == 2) ? W11
                        : (which == 3) ? W21 : (which == 4) ? W12 : W22;
        int layer = which >> 1, w12 = which & 1;
        float x = __ldg(&W[k * 128 + n]);
        __nv_bfloat16 h = __float2bfloat16_rn(x);
        float lo = x - __bfloat162float(h);
        g_wsplit[layer][w12][0][n * SW + k] = h;
        g_wsplit[layer][w12][1][n * SW + k] = __float2bfloat16_rn(lo);
    } else if (i < 6 * 16384 + NN) {
        g_cnt[i - 6 * 16384] = 0;
    } else if (i < 6 * 16384 + NN + NG * D) {
        out[i - 6 * 16384 - NN] = 0.f;
    }
}

// ---------------- CSR build ----------------
__global__ void k_count(const int* __restrict__ dst) {
    int e = blockIdx.x * blockDim.x + threadIdx.x;
    if (e < NE) atomicAdd(&g_cnt[dst[e]], 1);
}

__global__ void k_scan1() {
    int t = threadIdx.x, b = blockIdx.x;
    int i = b * 512 + t;
    int v = (i < NN) ? g_cnt[i] : 0;
    int x = v;
    #pragma unroll
    for (int o = 1; o < 32; o <<= 1) {
        int y = __shfl_up_sync(0xffffffffu, x, o);
        if ((t & 31) >= o) x += y;
    }
    __shared__ int ws[16];
    if ((t & 31) == 31) ws[t >> 5] = x;
    __syncthreads();
    if (t < 16) {
        int y = ws[t];
        #pragma unroll
        for (int o = 1; o < 16; o <<= 1) {
            int z = __shfl_up_sync(0xffffu, y, o);
            if (t >= o) y += z;
        }
        ws[t] = y;
    }
    __syncthreads();
    int off = (t >= 32) ? ws[(t >> 5) - 1] : 0;
    int incl = x + off;
    if (i < NN) g_pos[i] = incl - v;
    if (t == 511) g_bsum[b] = incl;
}

__global__ void k_scan2() {
    int t = threadIdx.x;
    int v = (t < SCAN_B) ? g_bsum[t] : 0;
    int x = v;
    #pragma unroll
    for (int o = 1; o < 32; o <<= 1) {
        int y = __shfl_up_sync(0xffffffffu, x, o);
        if ((t & 31) >= o) x += y;
    }
    __shared__ int ws[4];
    if ((t & 31) == 31) ws[t >> 5] = x;
    __syncthreads();
    if (t < 4) {
        int y = ws[t];
        #pragma unroll
        for (int o = 1; o < 4; o <<= 1) {
            int z = __shfl_up_sync(0xfu, y, o);
            if (t >= o) y += z;
        }
        ws[t] = y;
    }
    __syncthreads();
    int off = (t >= 32) ? ws[(t >> 5) - 1] : 0;
    g_boff[t] = x + off - v;
}

__global__ void k_scan3() {
    int t = threadIdx.x, b = blockIdx.x;
    int i = b * 512 + t;
    if (i < NN) {
        int p = g_pos[i] + g_boff[b];
        g_pos[i] = p;
        g_rowptr[i] = p;
    }
    if (b == 0 && t == 0) g_rowptr[NN] = NE;
}

__global__ void k_scatter(const int* __restrict__ src, const int* __restrict__ dst) {
    int e = blockIdx.x * blockDim.x + threadIdx.x;
    if (e < NE) {
        int d = dst[e];
        int p = atomicAdd(&g_pos[d], 1);
        g_col[p] = src[e];
    }
}

// ---------------- fused layer ----------------
// smem: A union (Ah/Al bf16 [64][SW] each = 34816 B, or pool fp32 [64][SA] = 33792 B)
//       + Wh/Wl bf16 [128][SW] each = 69632 B
#define A_BYTES (2 * 64 * SW * 2)           // 34816
#define LAYER_SMEM (A_BYTES + 2 * 128 * SW * 2)   // 104448

__device__ __forceinline__ void mma_bf16(float* c, const unsigned* a, const unsigned* b) {
    asm volatile("mma.sync.aligned.m16n8k16.row.col.f32.bf16.bf16.f32 "
        "{%0,%1,%2,%3}, {%4,%5,%6,%7}, {%8,%9}, {%0,%1,%2,%3};"
        : "+f"(c[0]), "+f"(c[1]), "+f"(c[2]), "+f"(c[3])
        : "r"(a[0]), "r"(a[1]), "r"(a[2]), "r"(a[3]), "r"(b[0]), "r"(b[1]));
}

// split float2 into bf16x2 hi (returned) and bf16x2 lo (out param)
__device__ __forceinline__ unsigned sp2(float2 x, unsigned& lo) {
    __nv_bfloat162 h = __float22bfloat162_rn(x);
    unsigned hu = *reinterpret_cast<unsigned*>(&h);
    float hx = __uint_as_float(hu << 16);
    float hy = __uint_as_float(hu & 0xffff0000u);
    __nv_bfloat162 l = __float22bfloat162_rn(make_float2(x.x - hx, x.y - hy));
    lo = *reinterpret_cast<unsigned*>(&l);
    return hu;
}

__device__ __forceinline__ void copy_w(const __nv_bfloat16* __restrict__ sh,
                                       const __nv_bfloat16* __restrict__ sl,
                                       __nv_bfloat16* dh, __nv_bfloat16* dl, int t) {
    const float4* s0 = (const float4*)sh;
    const float4* s1 = (const float4*)sl;
    float4* d0 = (float4*)dh;
    float4* d1 = (float4*)dl;
    #pragma unroll
    for (int i = t; i < 128 * SW * 2 / 16; i += 512) {
        d0[i] = __ldg(&s0[i]);
        d1[i] = __ldg(&s1[i]);
    }
}

__global__ void __launch_bounds__(512, 2)
k_layer(const float* __restrict__ hin, const float* __restrict__ eps, int layer,
        const float* __restrict__ B1, const float* __restrict__ B2,
        float* __restrict__ hout,
        const int* __restrict__ gid, float* __restrict__ out) {
    extern __shared__ float sm[];
    __nv_bfloat16* Ah = (__nv_bfloat16*)sm;          // [64][SW]
    __nv_bfloat16* Al = Ah + 64 * SW;
    __nv_bfloat16* Wh = (__nv_bfloat16*)((char*)sm + A_BYTES);   // [128][SW]
    __nv_bfloat16* Wl = Wh + 128 * SW;
    float* Ps = sm;                                  // pool staging union [64][SA]

    const int t    = threadIdx.x;
    const int wid  = t >> 5;
    const int lane = t & 31;
    const int wm   = wid & 1;      // rows wm*32..+31
    const int wn   = wid >> 1;     // cols wn*16..+15
    const int grp  = lane >> 2;
    const int qid  = lane & 3;
    const int row0 = blockIdx.x * 64;

    // ---- gather z, split to bf16 hi/lo tiles; stage W1 hi/lo ----
    {
        const float4* hv = (const float4*)hin;
        float ev = 1.0f + __ldg(&eps[layer]);
        #pragma unroll
        for (int i = 0; i < 4; i++) {
            int r = wid * 4 + i;
            int node = row0 + r;
            float4 a = make_float4(0.f, 0.f, 0.f, 0.f);
            if (node < NN) {
                a = __ldg(&hv[node * 32 + lane]);
                a.x *= ev; a.y *= ev; a.z *= ev; a.w *= ev;
                int jb = g_rowptr[node];
                int je = g_rowptr[node + 1];
                int j = jb;
                for (; j + 4 <= je; j += 4) {
                    int s0 = g_col[j], s1 = g_col[j + 1], s2 = g_col[j + 2], s3 = g_col[j + 3];
                    float4 x0 = __ldg(&hv[s0 * 32 + lane]);
                    float4 x1 = __ldg(&hv[s1 * 32 + lane]);
                    float4 x2 = __ldg(&hv[s2 * 32 + lane]);
                    float4 x3 = __ldg(&hv[s3 * 32 + lane]);
                    a.x += x0.x + x1.x + x2.x + x3.x;
                    a.y += x0.y + x1.y + x2.y + x3.y;
                    a.z += x0.z + x1.z + x2.z + x3.z;
                    a.w += x0.w + x1.w + x2.w + x3.w;
                }
                for (; j < je; j++) {
                    int s = g_col[j];
                    float4 x = __ldg(&hv[s * 32 + lane]);
                    a.x += x.x; a.y += x.y; a.z += x.z; a.w += x.w;
                }
            }
            unsigned l0, l1;
            unsigned h0 = sp2(make_float2(a.x, a.y), l0);
            unsigned h1 = sp2(make_float2(a.z, a.w), l1);
            *(uint2*)&Ah[r * SW + lane * 4] = make_uint2(h0, h1);
            *(uint2*)&Al[r * SW + lane * 4] = make_uint2(l0, l1);
        }
    }
    copy_w(g_wsplit[layer][0][0], g_wsplit[layer][0][1], Wh, Wl, t);
    __syncthreads();

    float acc[2][2][4];
    #pragma unroll
    for (int mt = 0; mt < 2; mt++)
        #pragma unroll
        for (int nt = 0; nt < 2; nt++)
            #pragma unroll
            for (int q = 0; q < 4; q++) acc[mt][nt][q] = 0.f;

    // ---- GEMM 1: pure LDS + HMMA ----
    #pragma unroll
    for (int kk = 0; kk < 8; kk++) {
        int k0 = kk * 16;
        unsigned ah[2][4], al[2][4];
        #pragma unroll
        for (int mt = 0; mt < 2; mt++) {
            const __nv_bfloat16* ap = &Ah[(wm * 32 + mt * 16 + grp) * SW + k0 + 2 * qid];
            const __nv_bfloat16* aq = &Al[(wm * 32 + mt * 16 + grp) * SW + k0 + 2 * qid];
            ah[mt][0] = *(const unsigned*)ap;
            ah[mt][1] = *(const unsigned*)(ap + 8 * SW);
            ah[mt][2] = *(const unsigned*)(ap + 8);
            ah[mt][3] = *(const unsigned*)(ap + 8 * SW + 8);
            al[mt][0] = *(const unsigned*)aq;
            al[mt][1] = *(const unsigned*)(aq + 8 * SW);
            al[mt][2] = *(const unsigned*)(aq + 8);
            al[mt][3] = *(const unsigned*)(aq + 8 * SW + 8);
        }
        #pragma unroll
        for (int nt = 0; nt < 2; nt++) {
            int cb = wn * 16 + nt * 8;
            const __nv_bfloat16* wp = &Wh[(cb + grp) * SW + k0 + 2 * qid];
            const __nv_bfloat16* wq = &Wl[(cb + grp) * SW + k0 + 2 * qid];
            unsigned bh[2], bl[2];
            bh[0] = *(const unsigned*)wp;
            bh[1] = *(const unsigned*)(wp + 8);
            bl[0] = *(const unsigned*)wq;
            bl[1] = *(const unsigned*)(wq + 8);
            #pragma unroll
            for (int mt = 0; mt < 2; mt++) {
                mma_bf16(acc[mt][nt], ah[mt], bh);
                mma_bf16(acc[mt][nt], al[mt], bh);
                mma_bf16(acc[mt][nt], ah[mt], bl);
            }
        }
    }

    __syncthreads();

    // ---- epilogue 1: relu + split -> Ah/Al; stage W2 ----
    #pragma unroll
    for (int mt = 0; mt < 2; mt++) {
        int r0 = wm * 32 + mt * 16 + grp;
        #pragma unroll
        for (int nt = 0; nt < 2; nt++) {
            int c = wn * 16 + nt * 8 + qid * 2;
            float b0 = __ldg(&B1[c]);
            float b1v = __ldg(&B1[c + 1]);
            float2 v0 = make_float2(fmaxf(acc[mt][nt][0] + b0, 0.f), fmaxf(acc[mt][nt][1] + b1v, 0.f));
            float2 v1 = make_float2(fmaxf(acc[mt][nt][2] + b0, 0.f), fmaxf(acc[mt][nt][3] + b1v, 0.f));
            unsigned l0, l1;
            unsigned h0 = sp2(v0, l0);
            unsigned h1 = sp2(v1, l1);
            *(unsigned*)&Ah[r0 * SW + c] = h0;
            *(unsigned*)&Al[r0 * SW + c] = l0;
            *(unsigned*)&Ah[(r0 + 8) * SW + c] = h1;
            *(unsigned*)&Al[(r0 + 8) * SW + c] = l1;
        }
    }
    copy_w(g_wsplit[layer][1][0], g_wsplit[layer][1][1], Wh, Wl, t);
    __syncthreads();

    #pragma unroll
    for (int mt = 0; mt < 2; mt++)
        #pragma unroll
        for (int nt = 0; nt < 2; nt++)
            #pragma unroll
            for (int q = 0; q < 4; q++) acc[mt][nt][q] = 0.f;

    // ---- GEMM 2 ----
    #pragma unroll
    for (int kk = 0; kk < 8; kk++) {
        int k0 = kk * 16;
        unsigned ah[2][4], al[2][4];
        #pragma unroll
        for (int mt = 0; mt < 2; mt++) {
            const __nv_bfloat16* ap = &Ah[(wm * 32 + mt * 16 + grp) * SW + k0 + 2 * qid];
            const __nv_bfloat16* aq = &Al[(wm * 32 + mt * 16 + grp) * SW + k0 + 2 * qid];
            ah[mt][0] = *(const unsigned*)ap;
            ah[mt][1] = *(const unsigned*)(ap + 8 * SW);
            ah[mt][2] = *(const unsigned*)(ap + 8);
            ah[mt][3] = *(const unsigned*)(ap + 8 * SW + 8);
            al[mt][0] = *(const unsigned*)aq;
            al[mt][1] = *(const unsigned*)(aq + 8 * SW);
            al[mt][2] = *(const unsigned*)(aq + 8);
            al[mt][3] = *(const unsigned*)(aq + 8 * SW + 8);
        }
        #pragma unroll
        for (int nt = 0; nt < 2; nt++) {
            int cb = wn * 16 + nt * 8;
            const __nv_bfloat16* wp = &Wh[(cb + grp) * SW + k0 + 2 * qid];
            const __nv_bfloat16* wq = &Wl[(cb + grp) * SW + k0 + 2 * qid];
            unsigned bh[2], bl[2];
            bh[0] = *(const unsigned*)wp;
            bh[1] = *(const unsigned*)(wp + 8);
            bl[0] = *(const unsigned*)wq;
            bl[1] = *(const unsigned*)(wq + 8);
            #pragma unroll
            for (int mt = 0; mt < 2; mt++) {
                mma_bf16(acc[mt][nt], ah[mt], bh);
                mma_bf16(acc[mt][nt], al[mt], bh);
                mma_bf16(acc[mt][nt], ah[mt], bl);
            }
        }
    }

    // ---- epilogue 2 ----
    if (hout) {
        #pragma unroll
        for (int mt = 0; mt < 2; mt++) {
            int r0 = row0 + wm * 32 + mt * 16 + grp;
            #pragma unroll
            for (int nt = 0; nt < 2; nt++) {
                int c = wn * 16 + nt * 8 + qid * 2;
                float b0 = __ldg(&B2[c]);
                float b1v = __ldg(&B2[c + 1]);
                if (r0 < NN)
                    *(float2*)&hout[r0 * 128 + c] =
                        make_float2(acc[mt][nt][0] + b0, acc[mt][nt][1] + b1v);
                if (r0 + 8 < NN)
                    *(float2*)&hout[(r0 + 8) * 128 + c] =
                        make_float2(acc[mt][nt][2] + b0, acc[mt][nt][3] + b1v);
            }
        }
    } else {
        __syncthreads();   // done reading Ah/Al; reuse as fp32 staging
        #pragma unroll
        for (int mt = 0; mt < 2; mt++) {
            int r0 = wm * 32 + mt * 16 + grp;
            #pragma unroll
            for (int nt = 0; nt < 2; nt++) {
                int c = wn * 16 + nt * 8 + qid * 2;
                float b0 = __ldg(&B2[c]);
                float b1v = __ldg(&B2[c + 1]);
                *(float2*)&Ps[r0 * SA + c] =
                    make_float2(acc[mt][nt][0] + b0, acc[mt][nt][1] + b1v);
                *(float2*)&Ps[(r0 + 8) * SA + c] =
                    make_float2(acc[mt][nt][2] + b0, acc[mt][nt][3] + b1v);
            }
        }
        __syncthreads();
        int gg = t >> 7;
        int c  = t & 127;
        float pacc = 0.f;
        int cur = -1;
        for (int r = gg * 16; r < gg * 16 + 16; r++) {
            int node = row0 + r;
            if (node >= NN) break;
            int g = __ldg(&gid[node]);
            if (g != cur) {
                if (cur >= 0) atomicAdd(&out[cur * 128 + c], pacc);
                cur = g;
                pacc = 0.f;
            }
            pacc += Ps[r * SA + c];
        }
        if (cur >= 0) atomicAdd(&out[cur * 128 + c], pacc);
    }
}

// ---------------- launch ----------------
extern "C" void kernel_launch(void* const* d_in, const int* in_sizes, int n_in,
                              void* d_out, int out_size) {
    const float* feats = (const float*)d_in[0];
    const int*   esrc  = (const int*)d_in[1];
    const int*   edst  = (const int*)d_in[2];
    const int*   gid   = (const int*)d_in[3];
    const float* eps   = (const float*)d_in[4];
    const float* W1[3] = {(const float*)d_in[5],  (const float*)d_in[9],  (const float*)d_in[13]};
    const float* B1[3] = {(const float*)d_in[6],  (const float*)d_in[10], (const float*)d_in[14]};
    const float* W2[3] = {(const float*)d_in[7],  (const float*)d_in[11], (const float*)d_in[15]};
    const float* B2[3] = {(const float*)d_in[8],  (const float*)d_in[12], (const float*)d_in[16]};
    float* out = (float*)d_out;
    (void)in_sizes; (void)n_in; (void)out_size;

    cudaFuncSetAttribute(k_layer, cudaFuncAttributeMaxDynamicSharedMemorySize, LAYER_SMEM);

    float* hA; cudaGetSymbolAddress((void**)&hA, g_hA);
    float* hB; cudaGetSymbolAddress((void**)&hB, g_hB);

    int initN = 6 * 16384 + NN + NG * D;
    k_init<<<(initN + 255) / 256, 256>>>(W1[0], W2[0], W1[1], W2[1], W1[2], W2[2], out);

    k_count<<<(NE + 255) / 256, 256>>>(edst);
    k_scan1<<<SCAN_B, 512>>>();
    k_scan2<<<1, 128>>>();
    k_scan3<<<SCAN_B, 512>>>();
    k_scatter<<<(NE + 255) / 256, 256>>>(esrc, edst);

    int grid = (NN + 63) / 64;
    k_layer<<<grid, 512, LAYER_SMEM>>>(feats, eps, 0, B1[0], B2[0], hA, gid, out);
    k_layer<<<grid, 512, LAYER_SMEM>>>(hA,    eps, 1, B1[1], B2[1], hB, gid, out);
    k_layer<<<grid, 512, LAYER_SMEM>>>(hB,    eps, 2, B1[2], B2[2], nullptr, gid, out);
}